// round 15
// baseline (speedup 1.0000x reference)
#include <cuda_runtime.h>
#include <cuda_fp16.h>
#include <math.h>
#include <stdint.h>

#define N_NODES 50000
#define N_PAD   53248            // padded for int4 scan reads
#define N_EDGES 800000
#define E_TOT   (N_EDGES + N_NODES)   // with self loops
#define HID     128
#define NEG_SLOPE 0.2f
#define EPS 1e-16f
#define HALF_N  25088            // pipeline split point (multiple of 128)

#define M_TILE   128
#define BK 32                 // k (fp16 elems) per chunk
#define A_PH 40               // half pitch for A tiles (32 + 8 pad) -> 80B rows
#define B_PH 136              // half pitch for B chunk (128 + 8)    -> 272B rows
#define GEMM_DYN_SMEM ((2 * M_TILE * A_PH + BK * B_PH) * 2)   // 29184 B

// ---------------- scratch (device globals; no allocation allowed) -----------
__device__ __half  g_xh[2 * (size_t)N_NODES * HID]; // x per layer parity (fp16)
__device__ float   g_h [(size_t)N_NODES * HID];     // layer activations (fp32)
__device__ float   g_as[2 * N_NODES];
__device__ float   g_ad[2 * N_NODES];
__device__ __half  g_wh[3 * HID * HID];             // W fp16 image: [l][k][n]
__device__ int     g_deg[N_PAD];
__device__ int     g_off[N_NODES + 1];
__device__ int     g_cur[N_NODES];
__device__ int     g_csrc[E_TOT];

// ---------------- helpers -----------------------------------------------------
__device__ __forceinline__ void mma_f16(float* d, const uint32_t* a, const uint32_t* b) {
    asm volatile(
        "mma.sync.aligned.m16n8k16.row.col.f32.f16.f16.f32 "
        "{%0,%1,%2,%3}, {%4,%5,%6,%7}, {%8,%9}, {%0,%1,%2,%3};"
        : "+f"(d[0]), "+f"(d[1]), "+f"(d[2]), "+f"(d[3])
        : "r"(a[0]), "r"(a[1]), "r"(a[2]), "r"(a[3]), "r"(b[0]), "r"(b[1]));
}
#define LDSM_X4(R0, R1, R2, R3, ADDR) \
    asm volatile("ldmatrix.sync.aligned.m8n8.x4.shared.b16 {%0,%1,%2,%3}, [%4];" \
        : "=r"(R0), "=r"(R1), "=r"(R2), "=r"(R3) : "r"(ADDR))
#define LDSM_X4T(R0, R1, R2, R3, ADDR) \
    asm volatile("ldmatrix.sync.aligned.m8n8.x4.trans.shared.b16 {%0,%1,%2,%3}, [%4];" \
        : "=r"(R0), "=r"(R1), "=r"(R2), "=r"(R3) : "r"(ADDR))

// ---------------- prep: W -> plain fp16 image [l][k][n] ----------------------
__global__ void prep_w_kernel(const float* __restrict__ Ws) {
    int i = blockIdx.x * blockDim.x + threadIdx.x;
    if (i >= 3 * HID * HID / 2) return;
    float2 v = ((const float2*)Ws)[i];
    ((__half2*)g_wh)[i] = __floats2half2_rn(v.x, v.y);
}

// ---------------- CSR build (4 edges/thread) ----------------------------------
__global__ void count_kernel(const int* __restrict__ ei) {
    int t = blockIdx.x * blockDim.x + threadIdx.x;
    if (t >= N_EDGES / 4) return;
    int4 d4 = ((const int4*)(ei + N_EDGES))[t];
    atomicAdd(&g_deg[d4.x], 1);
    atomicAdd(&g_deg[d4.y], 1);
    atomicAdd(&g_deg[d4.z], 1);
    atomicAdd(&g_deg[d4.w], 1);
}
__global__ void scan_kernel() {
    __shared__ int warp_sums[32];
    __shared__ int s_carry;
    int tid = threadIdx.x, lane = tid & 31, wid = tid >> 5;
    if (tid == 0) { g_off[0] = 0; s_carry = 0; }
    __syncthreads();
    for (int base = 0; base < N_NODES; base += 4096) {
        int i = base + tid * 4;
        int4 v = *(const int4*)(g_deg + i);
        int sl = (i < N_NODES) ? 1 : 0;
        int t0 = v.x + sl, t1 = t0 + v.y + sl, t2 = t1 + v.z + sl, t3 = t2 + v.w + sl;
        int x = t3;
        #pragma unroll
        for (int d = 1; d < 32; d <<= 1) {
            int t = __shfl_up_sync(0xffffffffu, x, d);
            if (lane >= d) x += t;
        }
        if (lane == 31) warp_sums[wid] = x;
        __syncthreads();
        if (wid == 0) {
            int w = warp_sums[lane];
            #pragma unroll
            for (int d = 1; d < 32; d <<= 1) {
                int t = __shfl_up_sync(0xffffffffu, w, d);
                if (lane >= d) w += t;
            }
            warp_sums[lane] = w;
        }
        __syncthreads();
        int excl = x - t3 + ((wid > 0) ? warp_sums[wid - 1] : 0) + s_carry;
        if (i < N_NODES) {
            g_off[i + 1] = excl + t0; g_cur[i + 0] = excl;
            g_off[i + 2] = excl + t1; g_cur[i + 1] = excl + t0;
            g_off[i + 3] = excl + t2; g_cur[i + 2] = excl + t1;
            g_off[i + 4] = excl + t3; g_cur[i + 3] = excl + t2;
        }
        __syncthreads();
        if (tid == 1023) s_carry = excl + t3;
        __syncthreads();
    }
}
__global__ void fill_kernel(const int* __restrict__ ei) {
    int t = blockIdx.x * blockDim.x + threadIdx.x;
    if (t < N_EDGES / 4) {
        int4 s4 = ((const int4*)ei)[t];
        int4 d4 = ((const int4*)(ei + N_EDGES))[t];
        g_csrc[atomicAdd(&g_cur[d4.x], 1)] = s4.x;
        g_csrc[atomicAdd(&g_cur[d4.y], 1)] = s4.y;
        g_csrc[atomicAdd(&g_cur[d4.z], 1)] = s4.z;
        g_csrc[atomicAdd(&g_cur[d4.w], 1)] = s4.w;
    } else {
        int node = t - N_EDGES / 4;
        if (node < N_NODES)
            g_csrc[atomicAdd(&g_cur[node], 1)] = node;
    }
}

// ---------------- GEMM: fp16 m16n8k16 2-term, ldmatrix fragment loads --------
__global__ void __launch_bounds__(256, 2)
gemm_mma_kernel(const float* __restrict__ in, const __half* __restrict__ Wh,
                const float* __restrict__ a_s, const float* __restrict__ a_d,
                int m_base, int buf)
{
    extern __shared__ __half dsm[];
    __half* sAh = dsm;                        // [M_TILE][A_PH]
    __half* sAl = sAh + M_TILE * A_PH;        // [M_TILE][A_PH]
    __half* sB  = sAl + M_TILE * A_PH;        // [BK][B_PH]

    __shared__ float s_as[HID], s_ad[HID];
    __shared__ float s_ps[2][M_TILE], s_pd[2][M_TILE];

    int tid = threadIdx.x, lane = tid & 31, wid = tid >> 5;
    int wm = wid & 3;
    int wn = wid >> 2;
    int m0 = m_base + blockIdx.x * M_TILE;
    int q = lane & 3, g = lane >> 2;

    __half* xh_out = g_xh + (size_t)buf * N_NODES * HID;
    float*  as_out = g_as + buf * N_NODES;
    float*  ad_out = g_ad + buf * N_NODES;

    for (int i = tid; i < HID; i += 256) { s_as[i] = a_s[i]; s_ad[i] = a_d[i]; }

    int a_row = tid >> 3;
    int a_kq  = (tid & 7) * 4;

    int l15 = lane & 15;
    int khalf = (lane >> 4) * 8;
    uint32_t aH_base = (uint32_t)__cvta_generic_to_shared(sAh)
                     + (uint32_t)(((wm * 32 + l15) * A_PH + khalf) * 2);
    uint32_t aL_base = aH_base + (uint32_t)(M_TILE * A_PH * 2);
    int b_krow = (lane & 7) + ((lane & 8) ? 8 : 0);
    int b_noff = (lane & 16) ? 8 : 0;
    uint32_t b_base = (uint32_t)__cvta_generic_to_shared(sB)
                    + (uint32_t)((b_krow * B_PH + wn * 64 + b_noff) * 2);

    float acc[2][8][4];
    #pragma unroll
    for (int mi = 0; mi < 2; mi++)
        #pragma unroll
        for (int ni = 0; ni < 8; ni++)
            #pragma unroll
            for (int t = 0; t < 4; t++) acc[mi][ni][t] = 0.f;

    const uint4* wh4 = (const uint4*)Wh;

    float4 rA[4]; uint4 rB[2];
    #pragma unroll
    for (int it = 0; it < 4; it++) {
        int gr = m0 + it * 32 + a_row;
        rA[it] = make_float4(0.f, 0.f, 0.f, 0.f);
        if (gr < N_NODES) rA[it] = *(const float4*)(in + (size_t)gr * HID + a_kq);
    }
    rB[0] = wh4[tid];
    rB[1] = wh4[tid + 256];

    #pragma unroll
    for (int c = 0; c < 4; c++) {
        #pragma unroll
        for (int it = 0; it < 4; it++) {
            float4 v = rA[it];
            __half2 h01 = __floats2half2_rn(v.x, v.y);
            __half2 h23 = __floats2half2_rn(v.z, v.w);
            float2 f01 = __half22float2(h01);
            float2 f23 = __half22float2(h23);
            __half2 l01 = __floats2half2_rn(v.x - f01.x, v.y - f01.y);
            __half2 l23 = __floats2half2_rn(v.z - f23.x, v.w - f23.y);
            int row = it * 32 + a_row;
            uint32_t* ph = (uint32_t*)&sAh[row * A_PH + a_kq];
            uint32_t* pl = (uint32_t*)&sAl[row * A_PH + a_kq];
            ph[0] = *(uint32_t*)&h01; ph[1] = *(uint32_t*)&h23;
            pl[0] = *(uint32_t*)&l01; pl[1] = *(uint32_t*)&l23;
        }
        {
            int t0 = tid, t1 = tid + 256;
            int r0 = t0 >> 4, c0 = (t0 & 15) * 8;
            int r1 = t1 >> 4, c1 = (t1 & 15) * 8;
            *(uint4*)&sB[r0 * B_PH + c0] = rB[0];
            *(uint4*)&sB[r1 * B_PH + c1] = rB[1];
        }
        __syncthreads();

        if (c < 3) {
            #pragma unroll
            for (int it = 0; it < 4; it++) {
                int gr = m0 + it * 32 + a_row;
                rA[it] = make_float4(0.f, 0.f, 0.f, 0.f);
                if (gr < N_NODES)
                    rA[it] = *(const float4*)(in + (size_t)gr * HID + (c + 1) * BK + a_kq);
            }
            rB[0] = wh4[(c + 1) * 512 + tid];
            rB[1] = wh4[(c + 1) * 512 + tid + 256];
        }

        #pragma unroll
        for (int ks = 0; ks < 2; ks++) {
            uint32_t ah[2][4], al[2][4], b[8][2];
            #pragma unroll
            for (int mi = 0; mi < 2; mi++) {
                uint32_t off = (uint32_t)((mi * 16 * A_PH + ks * 16) * 2);
                LDSM_X4(ah[mi][0], ah[mi][1], ah[mi][2], ah[mi][3], aH_base + off);
                LDSM_X4(al[mi][0], al[mi][1], al[mi][2], al[mi][3], aL_base + off);
            }
            #pragma unroll
            for (int n2 = 0; n2 < 4; n2++) {
                uint32_t off = (uint32_t)((ks * 16 * B_PH + n2 * 16) * 2);
                LDSM_X4T(b[2 * n2][0], b[2 * n2][1], b[2 * n2 + 1][0], b[2 * n2 + 1][1],
                         b_base + off);
            }
            #pragma unroll
            for (int ni = 0; ni < 8; ni++)
                #pragma unroll
                for (int mi = 0; mi < 2; mi++) {
                    mma_f16(acc[mi][ni], ah[mi], b[ni]);
                    mma_f16(acc[mi][ni], al[mi], b[ni]);
                }
        }
        __syncthreads();
    }

    // epilogue
    #pragma unroll
    for (int mi = 0; mi < 2; mi++) {
        int rA_ = wm * 32 + g + mi * 16;
        int rB_ = rA_ + 8;
        int gA = m0 + rA_, gB = m0 + rB_;
        float sA_ = 0.f, dA_ = 0.f, sB_ = 0.f, dB_ = 0.f;
        #pragma unroll
        for (int ni = 0; ni < 8; ni++) {
            int cc = wn * 64 + ni * 8 + q * 2;
            float v0 = acc[mi][ni][0], v1 = acc[mi][ni][1];
            float v2 = acc[mi][ni][2], v3 = acc[mi][ni][3];
            sA_ += v0 * s_as[cc] + v1 * s_as[cc + 1];
            dA_ += v0 * s_ad[cc] + v1 * s_ad[cc + 1];
            sB_ += v2 * s_as[cc] + v3 * s_as[cc + 1];
            dB_ += v2 * s_ad[cc] + v3 * s_ad[cc + 1];
            if (gA < N_NODES)
                *(__half2*)(xh_out + (size_t)gA * HID + cc) = __floats2half2_rn(v0, v1);
            if (gB < N_NODES)
                *(__half2*)(xh_out + (size_t)gB * HID + cc) = __floats2half2_rn(v2, v3);
        }
        sA_ += __shfl_xor_sync(0xffffffffu, sA_, 1); sA_ += __shfl_xor_sync(0xffffffffu, sA_, 2);
        dA_ += __shfl_xor_sync(0xffffffffu, dA_, 1); dA_ += __shfl_xor_sync(0xffffffffu, dA_, 2);
        sB_ += __shfl_xor_sync(0xffffffffu, sB_, 1); sB_ += __shfl_xor_sync(0xffffffffu, sB_, 2);
        dB_ += __shfl_xor_sync(0xffffffffu, dB_, 1); dB_ += __shfl_xor_sync(0xffffffffu, dB_, 2);
        if (q == 0) {
            s_ps[wn][rA_] = sA_; s_pd[wn][rA_] = dA_;
            s_ps[wn][rB_] = sB_; s_pd[wn][rB_] = dB_;
        }
    }
    __syncthreads();
    if (tid < M_TILE) {
        int gm = m0 + tid;
        if (gm < N_NODES) {
            as_out[gm] = s_ps[0][tid] + s_ps[1][tid];
            ad_out[gm] = s_pd[0][tid] + s_pd[1][tid];
        }
    }
}

// ---------------- aggregation: warp/node, online softmax, smem pair bcast ----
__device__ __forceinline__ float leaky(float t) {
    return t > 0.f ? t : NEG_SLOPE * t;
}

__global__ __launch_bounds__(256) void agg_kernel(
    const float* __restrict__ bias, float* __restrict__ dout, int last,
    int node_base, int node_end, int buf)
{
    __shared__ uint2 s_ew[8][32];
    int node = node_base + ((blockIdx.x * blockDim.x + threadIdx.x) >> 5);
    int lane = threadIdx.x & 31;
    int wid  = (threadIdx.x >> 5) & 7;
    if (node >= node_end) return;
    int start = g_off[node];
    int end   = g_off[node + 1];

    const __half* xh = g_xh + (size_t)buf * N_NODES * HID;
    const float*  as = g_as + buf * N_NODES;
    float adv = g_ad[buf * N_NODES + node];

    float m = -INFINITY;
    float den = 0.f;
    float4 acc = make_float4(0.f, 0.f, 0.f, 0.f);

    for (int i0 = start; i0 < end; i0 += 32) {
        int n = end - i0; if (n > 32) n = 32;
        int   s_l = 0; float e_l = -INFINITY;
        if (lane < n) {
            s_l = g_csrc[i0 + lane];
            e_l = leaky(as[s_l] + adv);
        }
        float bm = e_l;
        #pragma unroll
        for (int o = 16; o; o >>= 1) bm = fmaxf(bm, __shfl_xor_sync(0xffffffffu, bm, o));
        if (bm > m) {
            float f = __expf(m - bm);
            acc.x *= f; acc.y *= f; acc.z *= f; acc.w *= f;
            den *= f;
            m = bm;
        }
        float w_l = (lane < n) ? __expf(e_l - m) : 0.f;
        den += w_l;
        s_ew[wid][lane] = make_uint2(__float_as_uint(w_l), (uint32_t)s_l);
        __syncwarp();
        for (int j = 0; j < n; j++) {
            uint2 ew = s_ew[wid][j];
            float w = __uint_as_float(ew.x);
            int   s = (int)ew.y;
            uint2 raw = *((const uint2*)(xh + (size_t)s * HID) + lane);
            float2 f0 = __half22float2(*(const __half2*)&raw.x);
            float2 f1 = __half22float2(*(const __half2*)&raw.y);
            acc.x += w * f0.x; acc.y += w * f0.y;
            acc.z += w * f1.x; acc.w += w * f1.y;
        }
        __syncwarp();
    }
    #pragma unroll
    for (int o = 16; o; o >>= 1) den += __shfl_xor_sync(0xffffffffu, den, o);
    float inv = 1.0f / (den + EPS);

    float4 b4 = *(const float4*)(bias + lane * 4);
    acc.x = acc.x * inv + b4.x; acc.y = acc.y * inv + b4.y;
    acc.z = acc.z * inv + b4.z; acc.w = acc.w * inv + b4.w;

    if (last) {
        *(float4*)(dout + (size_t)node * HID + lane * 4) = acc;
    } else {
        acc.x = fmaxf(acc.x, 0.f); acc.y = fmaxf(acc.y, 0.f);
        acc.z = fmaxf(acc.z, 0.f); acc.w = fmaxf(acc.w, 0.f);
        *(float4*)(g_h + (size_t)node * HID + lane * 4) = acc;
    }
}

// ---------------- launch -----------------------------------------------------
extern "C" void kernel_launch(void* const* d_in, const int* in_sizes, int n_in,
                              void* d_out, int out_size)
{
    const float* z     = (const float*)d_in[0];
    const int*   ei    = (const int*)  d_in[1];
    const float* Ws    = (const float*)d_in[2];
    const float* a_src = (const float*)d_in[3];
    const float* a_dst = (const float*)d_in[4];
    const float* bias  = (const float*)d_in[5];
    float* out = (float*)d_out;

    float*  d_gh;  cudaGetSymbolAddress((void**)&d_gh, g_h);
    __half* d_wh;  cudaGetSymbolAddress((void**)&d_wh, g_wh);
    int*    d_deg; cudaGetSymbolAddress((void**)&d_deg, g_deg);

    // one-time host-side resources (no device allocation)
    static cudaStream_t s2 = nullptr;
    static cudaEvent_t ev[8] = {};
    if (s2 == nullptr) {
        cudaStreamCreateWithFlags(&s2, cudaStreamNonBlocking);
        for (int i = 0; i < 8; i++)
            cudaEventCreateWithFlags(&ev[i], cudaEventDisableTiming);
    }
    cudaEvent_t evFork = ev[0], evCSR = ev[1], evG0 = ev[2];
    cudaEvent_t evG1A = ev[3], evG1B = ev[4], evG2A = ev[5], evG2B = ev[6];

    const int GA_BLK = HALF_N / M_TILE;                        // 196
    const int GB_BLK = (N_NODES - HALF_N + M_TILE - 1) / M_TILE; // 195
    const int G_BLK  = (N_NODES + M_TILE - 1) / M_TILE;        // 391
    const int AA_BLK = (HALF_N * 32 + 255) / 256;              // 3136
    const int AB_BLK = ((N_NODES - HALF_N) * 32 + 255) / 256;  // 3114
    const int AF_BLK = (N_NODES * 32 + 255) / 256;             // 6250

    // fork: CSR chain on s2, concurrent with prep_w + gemm0 on main
    cudaEventRecord(evFork, 0);
    cudaStreamWaitEvent(s2, evFork, 0);
    cudaMemsetAsync(d_deg, 0, N_PAD * sizeof(int), s2);
    count_kernel<<<(N_EDGES / 4 + 255) / 256, 256, 0, s2>>>(ei);
    scan_kernel<<<1, 1024, 0, s2>>>();
    fill_kernel<<<(N_EDGES / 4 + N_NODES + 255) / 256, 256, 0, s2>>>(ei);
    cudaEventRecord(evCSR, s2);

    // main: layer-0 linear transform (full), buf 0
    prep_w_kernel<<<(3 * HID * HID / 2 + 255) / 256, 256>>>(Ws);
    gemm_mma_kernel<<<G_BLK, 256, GEMM_DYN_SMEM>>>(z, d_wh, a_src, a_dst, 0, 0);
    cudaEventRecord(evG0, 0);

    // agg0: half A on main (after CSR), half B on s2 (after gemm0)
    cudaStreamWaitEvent(0, evCSR, 0);
    agg_kernel<<<AA_BLK, 256>>>(bias, out, 0, 0, HALF_N, 0);
    cudaStreamWaitEvent(s2, evG0, 0);
    agg_kernel<<<AB_BLK, 256, 0, s2>>>(bias, out, 0, HALF_N, N_NODES, 0);

    // gemm1: half A on main (needs agg0A), half B on s2 (needs agg0B), buf 1
    gemm_mma_kernel<<<GA_BLK, 256, GEMM_DYN_SMEM>>>(
        d_gh, d_wh + HID * HID, a_src + HID, a_dst + HID, 0, 1);
    cudaEventRecord(evG1A, 0);
    gemm_mma_kernel<<<GB_BLK, 256, GEMM_DYN_SMEM, s2>>>(
        d_gh, d_wh + HID * HID, a_src + HID, a_dst + HID, HALF_N, 1);
    cudaEventRecord(evG1B, s2);

    // agg1: half A on main (needs gemm1 complete), half B on s2
    cudaStreamWaitEvent(0, evG1B, 0);
    agg_kernel<<<AA_BLK, 256>>>(bias + HID, out, 0, 0, HALF_N, 1);
    cudaStreamWaitEvent(s2, evG1A, 0);
    agg_kernel<<<AB_BLK, 256, 0, s2>>>(bias + HID, out, 0, HALF_N, N_NODES, 1);

    // gemm2: half A on main (needs agg1A), half B on s2 (needs agg1B), buf 0
    gemm_mma_kernel<<<GA_BLK, 256, GEMM_DYN_SMEM>>>(
        d_gh, d_wh + 2 * HID * HID, a_src + 2 * HID, a_dst + 2 * HID, 0, 0);
    cudaEventRecord(evG2A, 0);
    gemm_mma_kernel<<<GB_BLK, 256, GEMM_DYN_SMEM, s2>>>(
        d_gh, d_wh + 2 * HID * HID, a_src + 2 * HID, a_dst + 2 * HID, HALF_N, 0);
    cudaEventRecord(evG2B, s2);

    // agg2: full on main (needs gemm2 both halves); joins s2 back to main
    cudaStreamWaitEvent(0, evG2B, 0);
    agg_kernel<<<AF_BLK, 256>>>(bias + 2 * HID, out, 1, 0, N_NODES, 0);
}